// round 2
// baseline (speedup 1.0000x reference)
#include <cuda_runtime.h>

// Problem dims (fixed by the dataset)
#define BDIM 4
#define HDIM 16
#define SDIM 2048
#define DDIM 64
#define BH   (BDIM*HDIM)                  // 64
#define OUT_ELEMS ((size_t)BH*SDIM*DDIM)  // 8388608
#define NEG_INF_VAL (-1e14f)
#define SCALE 0.125f                      // 1/sqrt(64)

// ---------------------------------------------------------------------------
// Kernel 1: scores = mask ? (Q K^T * scale) : -1e14, written to attn buffer.
// Tile: 128 (q) x 128 (k), full D=64 reduction in one shot.
// Qs row-major [128][65] (pad 65), K tile transposed KsT [64][130] so the
// b-operand loads are contiguous float2s.
// ---------------------------------------------------------------------------
#define SMEM1_FLOATS (128*65 + 64*130)
#define SMEM1_BYTES  (SMEM1_FLOATS*4)

__global__ __launch_bounds__(256) void k_scores(
    const float* __restrict__ Q,
    const float* __restrict__ K,
    const int*   __restrict__ mask,
    float*       __restrict__ attn)
{
    extern __shared__ float sm[];
    float* Qs  = sm;              // [128][65]
    float* KsT = sm + 128*65;     // [64][130]

    const int bh = blockIdx.z;
    const int qt = blockIdx.y;
    const int kt = blockIdx.x;
    const int tid = threadIdx.x;

    const float* Qbase = Q + ((size_t)bh*SDIM + (size_t)qt*128) * DDIM;
    const float* Kbase = K + ((size_t)bh*SDIM + (size_t)kt*128) * DDIM;

    // Load Q tile: 128x64 floats = 2048 float4, 8 per thread.
    {
        const float4* Qv = (const float4*)Qbase;
        #pragma unroll
        for (int i = 0; i < 8; i++) {
            int e  = tid + i*256;
            int r  = e >> 4;
            int dc = e & 15;
            float4 v = Qv[r*16 + dc];
            float* dst = &Qs[r*65 + dc*4];
            dst[0] = v.x; dst[1] = v.y; dst[2] = v.z; dst[3] = v.w;
        }
        // Load K tile transposed: 128 rows x 32 float2 = 4096, 16 per thread.
        const float2* Kv = (const float2*)Kbase;
        #pragma unroll
        for (int i = 0; i < 16; i++) {
            int e  = tid + i*256;
            int r  = e >> 5;
            int dc = e & 31;
            float2 v = Kv[r*32 + dc];
            KsT[(2*dc  )*130 + r] = v.x;
            KsT[(2*dc+1)*130 + r] = v.y;
        }
    }
    __syncthreads();

    const int tx = tid & 15;   // k-block micro col (8 wide)
    const int ty = tid >> 4;   // q-block micro row (8 tall)

    float acc[8][8];
    #pragma unroll
    for (int i = 0; i < 8; i++)
        #pragma unroll
        for (int j = 0; j < 8; j++) acc[i][j] = 0.0f;

    #pragma unroll 8
    for (int k = 0; k < 64; k++) {
        float a[8];
        #pragma unroll
        for (int i = 0; i < 8; i++) a[i] = Qs[(ty*8+i)*65 + k];
        const float2* bp = (const float2*)&KsT[k*130 + tx*8];
        float2 b0 = bp[0], b1 = bp[1], b2 = bp[2], b3 = bp[3];
        float b[8] = {b0.x, b0.y, b1.x, b1.y, b2.x, b2.y, b3.x, b3.y};
        #pragma unroll
        for (int i = 0; i < 8; i++)
            #pragma unroll
            for (int j = 0; j < 8; j++)
                acc[i][j] += a[i] * b[j];
    }

    // Scale + mask + write (two float4 per row, coalesced).
    const size_t attn_base = (size_t)bh * SDIM * SDIM;
    const size_t mask_base = (size_t)(bh / HDIM) * SDIM * SDIM;
    const int col0 = kt*128 + tx*8;
    #pragma unroll
    for (int i = 0; i < 8; i++) {
        int row = qt*128 + ty*8 + i;
        const int4* m4 = (const int4*)&mask[mask_base + (size_t)row*SDIM + col0];
        int4 m0 = m4[0], m1 = m4[1];
        float4 o0, o1;
        o0.x = m0.x ? acc[i][0]*SCALE : NEG_INF_VAL;
        o0.y = m0.y ? acc[i][1]*SCALE : NEG_INF_VAL;
        o0.z = m0.z ? acc[i][2]*SCALE : NEG_INF_VAL;
        o0.w = m0.w ? acc[i][3]*SCALE : NEG_INF_VAL;
        o1.x = m1.x ? acc[i][4]*SCALE : NEG_INF_VAL;
        o1.y = m1.y ? acc[i][5]*SCALE : NEG_INF_VAL;
        o1.z = m1.z ? acc[i][6]*SCALE : NEG_INF_VAL;
        o1.w = m1.w ? acc[i][7]*SCALE : NEG_INF_VAL;
        float4* dst = (float4*)&attn[attn_base + (size_t)row*SDIM + col0];
        dst[0] = o0;
        dst[1] = o1;
    }
}

// ---------------------------------------------------------------------------
// Kernel 2: in-place row softmax over attn. One block (256 threads) per row.
// Each thread owns 8 elements (2 float4).
// ---------------------------------------------------------------------------
__global__ __launch_bounds__(256) void k_softmax(float* __restrict__ attn)
{
    const size_t row = blockIdx.x;
    float4* rp = (float4*)(attn + row * (size_t)SDIM);
    const int tid  = threadIdx.x;
    const int w    = tid >> 5;
    const int lane = tid & 31;

    float4 v0 = rp[tid];
    float4 v1 = rp[tid + 256];

    float m = fmaxf(fmaxf(fmaxf(v0.x, v0.y), fmaxf(v0.z, v0.w)),
                    fmaxf(fmaxf(v1.x, v1.y), fmaxf(v1.z, v1.w)));
    #pragma unroll
    for (int o = 16; o > 0; o >>= 1)
        m = fmaxf(m, __shfl_xor_sync(0xffffffffu, m, o));

    __shared__ float red[8];
    if (lane == 0) red[w] = m;
    __syncthreads();
    m = red[0];
    #pragma unroll
    for (int i = 1; i < 8; i++) m = fmaxf(m, red[i]);

    v0.x = __expf(v0.x - m); v0.y = __expf(v0.y - m);
    v0.z = __expf(v0.z - m); v0.w = __expf(v0.w - m);
    v1.x = __expf(v1.x - m); v1.y = __expf(v1.y - m);
    v1.z = __expf(v1.z - m); v1.w = __expf(v1.w - m);

    float s = (v0.x + v0.y) + (v0.z + v0.w) + (v1.x + v1.y) + (v1.z + v1.w);
    #pragma unroll
    for (int o = 16; o > 0; o >>= 1)
        s += __shfl_xor_sync(0xffffffffu, s, o);

    __syncthreads();   // everyone done reading red (max phase)
    if (lane == 0) red[w] = s;
    __syncthreads();
    s = red[0];
    #pragma unroll
    for (int i = 1; i < 8; i++) s += red[i];

    const float inv = 1.0f / s;
    v0.x *= inv; v0.y *= inv; v0.z *= inv; v0.w *= inv;
    v1.x *= inv; v1.y *= inv; v1.z *= inv; v1.w *= inv;
    rp[tid]       = v0;
    rp[tid + 256] = v1;
}

// ---------------------------------------------------------------------------
// Kernel 3: out = attn @ V.  Tile: 128 (q) x 64 (d), looping k in chunks of 64.
// As [128][65] padded; Vs [64][64] row-major (float4 friendly).
// Thread micro-tile: 8 rows x 4 cols.
// ---------------------------------------------------------------------------
#define SMEM3_FLOATS (128*65 + 64*64)
#define SMEM3_BYTES  (SMEM3_FLOATS*4)

__global__ __launch_bounds__(256) void k_pv(
    const float* __restrict__ attn,
    const float* __restrict__ V,
    float*       __restrict__ out)
{
    extern __shared__ float sm[];
    float* As = sm;             // [128][65]
    float* Vs = sm + 128*65;    // [64][64]

    const int bh = blockIdx.y;
    const int qt = blockIdx.x;
    const int tid = threadIdx.x;
    const int tx = tid & 15;    // d micro col (4 wide)
    const int ty = tid >> 4;    // q micro row (8 tall)

    const float* Abase = attn + ((size_t)bh*SDIM + (size_t)qt*128) * SDIM;
    const float* Vbase = V + (size_t)bh * SDIM * DDIM;

    float acc[8][4];
    #pragma unroll
    for (int i = 0; i < 8; i++)
        #pragma unroll
        for (int j = 0; j < 4; j++) acc[i][j] = 0.0f;

    for (int kk = 0; kk < SDIM; kk += 64) {
        // Load attn tile 128x64: 2048 float4, 8 per thread.
        #pragma unroll
        for (int i = 0; i < 8; i++) {
            int e  = tid + i*256;
            int r  = e >> 4;
            int cc = e & 15;
            float4 v = *(const float4*)&Abase[(size_t)r*SDIM + kk + cc*4];
            float* dst = &As[r*65 + cc*4];
            dst[0] = v.x; dst[1] = v.y; dst[2] = v.z; dst[3] = v.w;
        }
        // Load V tile 64x64: 1024 float4, 4 per thread.
        #pragma unroll
        for (int i = 0; i < 4; i++) {
            int e  = tid + i*256;
            int r  = e >> 4;
            int cc = e & 15;
            *(float4*)&Vs[r*64 + cc*4] =
                *(const float4*)&Vbase[(size_t)(kk + r)*DDIM + cc*4];
        }
        __syncthreads();

        #pragma unroll 8
        for (int k = 0; k < 64; k++) {
            float a[8];
            #pragma unroll
            for (int i = 0; i < 8; i++) a[i] = As[(ty*8+i)*65 + k];
            float4 bv = *(const float4*)&Vs[k*64 + tx*4];
            #pragma unroll
            for (int i = 0; i < 8; i++) {
                acc[i][0] += a[i] * bv.x;
                acc[i][1] += a[i] * bv.y;
                acc[i][2] += a[i] * bv.z;
                acc[i][3] += a[i] * bv.w;
            }
        }
        __syncthreads();
    }

    #pragma unroll
    for (int i = 0; i < 8; i++) {
        int row = qt*128 + ty*8 + i;
        float4 o;
        o.x = acc[i][0]; o.y = acc[i][1]; o.z = acc[i][2]; o.w = acc[i][3];
        *(float4*)&out[((size_t)bh*SDIM + row)*DDIM + tx*4] = o;
    }
}

// ---------------------------------------------------------------------------
// Launch
// ---------------------------------------------------------------------------
extern "C" void kernel_launch(void* const* d_in, const int* in_sizes, int n_in,
                              void* d_out, int out_size)
{
    (void)in_sizes; (void)n_in; (void)out_size;
    const float* Q    = (const float*)d_in[0];
    const float* K    = (const float*)d_in[1];
    const float* V    = (const float*)d_in[2];
    const int*   mask = (const int*)d_in[3];

    float* out  = (float*)d_out;
    float* attn = out + OUT_ELEMS;   // reference returns (out, attn) concatenated

    cudaFuncSetAttribute(k_scores, cudaFuncAttributeMaxDynamicSharedMemorySize, SMEM1_BYTES);
    cudaFuncSetAttribute(k_pv,     cudaFuncAttributeMaxDynamicSharedMemorySize, SMEM3_BYTES);

    k_scores<<<dim3(SDIM/128, SDIM/128, BH), 256, SMEM1_BYTES>>>(Q, K, mask, attn);
    k_softmax<<<BH*SDIM, 256>>>(attn);
    k_pv<<<dim3(SDIM/128, BH), 256, SMEM3_BYTES>>>(attn, V, out);
}

// round 3
// speedup vs baseline: 1.0428x; 1.0428x over previous
#include <cuda_runtime.h>

// Problem dims (fixed by the dataset)
#define BDIM 4
#define HDIM 16
#define SDIM 2048
#define DDIM 64
#define BH   (BDIM*HDIM)                  // 64
#define OUT_ELEMS ((size_t)BH*SDIM*DDIM)  // 8388608
#define SCALE 0.125f                      // 1/sqrt(64)

// Row sums of unnormalized exp scores (scratch; allocation-free per rules).
__device__ float g_rowsum[(size_t)BH * SDIM];

// ---------------------------------------------------------------------------
// Kernel 1: attn_raw[q,k] = mask ? exp(scale * Q.K) : 0   (unnormalized)
//           g_rowsum[q]   = sum_k attn_raw[q,k]
// One block handles 128 q-rows x ALL 2048 k-cols (loop over 16 k-tiles).
// Smem: Qs[128][66] (float2-friendly), KsT[64][132] (float4-friendly, no
// bank conflicts on the b-operand LDS.128).
// ---------------------------------------------------------------------------
#define QP 66
#define KP 132
#define SMEM1_FLOATS (128*QP + 64*KP)
#define SMEM1_BYTES  (SMEM1_FLOATS*4)

__global__ __launch_bounds__(256, 2) void k_scores_exp(
    const float* __restrict__ Q,
    const float* __restrict__ K,
    const int*   __restrict__ mask,
    float*       __restrict__ attn)
{
    extern __shared__ float sm[];
    float* Qs  = sm;              // [128][QP]
    float* KsT = sm + 128*QP;     // [64][KP]

    const int bh  = blockIdx.y;
    const int qt  = blockIdx.x;
    const int tid = threadIdx.x;
    const int tx  = tid & 15;     // col micro group
    const int ty  = tid >> 4;     // row micro group (8 rows)

    // Load Q tile once: 128x64 floats = 2048 float4, 8 per thread.
    {
        const float4* Qv = (const float4*)(Q + ((size_t)bh*SDIM + (size_t)qt*128) * DDIM);
        #pragma unroll
        for (int i = 0; i < 8; i++) {
            int e  = tid + i*256;
            int r  = e >> 4;
            int dc = e & 15;
            float4 v = Qv[r*16 + dc];
            float* dst = &Qs[r*QP + dc*4];
            dst[0] = v.x; dst[1] = v.y; dst[2] = v.z; dst[3] = v.w;
        }
    }

    const size_t attn_base = (size_t)bh * SDIM * SDIM;
    const size_t mask_base = (size_t)(bh / HDIM) * SDIM * SDIM;
    const float* Kbh = K + (size_t)bh * SDIM * DDIM;

    float rs[8];
    #pragma unroll
    for (int i = 0; i < 8; i++) rs[i] = 0.0f;

    for (int kt = 0; kt < 16; kt++) {
        // Load K tile transposed: 128 rows x 32 float2, 16 per thread.
        {
            const float2* Kv = (const float2*)(Kbh + (size_t)kt*128*DDIM);
            #pragma unroll
            for (int i = 0; i < 16; i++) {
                int e  = tid + i*256;
                int r  = e >> 5;
                int dc = e & 31;
                float2 v = Kv[r*32 + dc];
                KsT[(2*dc  )*KP + r] = v.x;
                KsT[(2*dc+1)*KP + r] = v.y;
            }
        }
        __syncthreads();   // K (and Q on first iter) ready

        float acc[8][8];
        #pragma unroll
        for (int i = 0; i < 8; i++)
            #pragma unroll
            for (int j = 0; j < 8; j++) acc[i][j] = 0.0f;

        #pragma unroll 4
        for (int k0 = 0; k0 < 64; k0 += 2) {
            float2 a[8];
            #pragma unroll
            for (int i = 0; i < 8; i++)
                a[i] = *(const float2*)&Qs[(ty*8+i)*QP + k0];
            float4 b00 = *(const float4*)&KsT[ k0   *KP      + tx*4];
            float4 b01 = *(const float4*)&KsT[ k0   *KP + 64 + tx*4];
            float4 b10 = *(const float4*)&KsT[(k0+1)*KP      + tx*4];
            float4 b11 = *(const float4*)&KsT[(k0+1)*KP + 64 + tx*4];
            #pragma unroll
            for (int i = 0; i < 8; i++) {
                acc[i][0] += a[i].x * b00.x;  acc[i][1] += a[i].x * b00.y;
                acc[i][2] += a[i].x * b00.z;  acc[i][3] += a[i].x * b00.w;
                acc[i][4] += a[i].x * b01.x;  acc[i][5] += a[i].x * b01.y;
                acc[i][6] += a[i].x * b01.z;  acc[i][7] += a[i].x * b01.w;
                acc[i][0] += a[i].y * b10.x;  acc[i][1] += a[i].y * b10.y;
                acc[i][2] += a[i].y * b10.z;  acc[i][3] += a[i].y * b10.w;
                acc[i][4] += a[i].y * b11.x;  acc[i][5] += a[i].y * b11.y;
                acc[i][6] += a[i].y * b11.z;  acc[i][7] += a[i].y * b11.w;
            }
        }
        __syncthreads();   // all KsT reads done before next tile overwrites

        // mask + scale + exp + row-sum + store (coalesced float4 pairs)
        const int col0 = kt*128 + tx*4;        // cols col0..col0+3
        const int col1 = col0 + 64;            // cols col1..col1+3
        #pragma unroll
        for (int i = 0; i < 8; i++) {
            const int row = qt*128 + ty*8 + i;
            const size_t rbase = (size_t)row * SDIM;
            int4 m0 = *(const int4*)&mask[mask_base + rbase + col0];
            int4 m1 = *(const int4*)&mask[mask_base + rbase + col1];
            float4 e0, e1;
            e0.x = m0.x ? __expf(acc[i][0]*SCALE) : 0.0f;
            e0.y = m0.y ? __expf(acc[i][1]*SCALE) : 0.0f;
            e0.z = m0.z ? __expf(acc[i][2]*SCALE) : 0.0f;
            e0.w = m0.w ? __expf(acc[i][3]*SCALE) : 0.0f;
            e1.x = m1.x ? __expf(acc[i][4]*SCALE) : 0.0f;
            e1.y = m1.y ? __expf(acc[i][5]*SCALE) : 0.0f;
            e1.z = m1.z ? __expf(acc[i][6]*SCALE) : 0.0f;
            e1.w = m1.w ? __expf(acc[i][7]*SCALE) : 0.0f;
            rs[i] += ((e0.x + e0.y) + (e0.z + e0.w)) + ((e1.x + e1.y) + (e1.z + e1.w));
            *(float4*)&attn[attn_base + rbase + col0] = e0;
            *(float4*)&attn[attn_base + rbase + col1] = e1;
        }
    }

    // Reduce row sums across the 16 lanes sharing each row (within half-warp).
    #pragma unroll
    for (int o = 1; o < 16; o <<= 1)
        #pragma unroll
        for (int i = 0; i < 8; i++)
            rs[i] += __shfl_xor_sync(0xffffffffu, rs[i], o);

    if (tx == 0) {
        #pragma unroll
        for (int i = 0; i < 8; i++)
            g_rowsum[(size_t)bh*SDIM + qt*128 + ty*8 + i] = rs[i];
    }
}

// ---------------------------------------------------------------------------
// Kernel 2: out = (attn_raw * inv_rowsum) @ V, and rewrite attn normalized.
// Block: 128 q-rows x 64 d-cols, loop k in chunks of 64.
// ---------------------------------------------------------------------------
#define AP 66
#define SMEM3_FLOATS (128*AP + 64*64 + 128)
#define SMEM3_BYTES  (SMEM3_FLOATS*4)

__global__ __launch_bounds__(256, 2) void k_pv_norm(
    float*       __restrict__ attn,
    const float* __restrict__ V,
    float*       __restrict__ out)
{
    extern __shared__ float sm[];
    float* As   = sm;                    // [128][AP]
    float* Vs   = sm + 128*AP;           // [64][64]
    float* invs = sm + 128*AP + 64*64;   // [128]

    const int bh  = blockIdx.y;
    const int qt  = blockIdx.x;
    const int tid = threadIdx.x;
    const int tx  = tid & 15;    // d micro col (4 wide)
    const int ty  = tid >> 4;    // q micro row (8 tall)

    if (tid < 128)
        invs[tid] = 1.0f / g_rowsum[(size_t)bh*SDIM + qt*128 + tid];

    float* Abase = attn + ((size_t)bh*SDIM + (size_t)qt*128) * SDIM;
    const float* Vbase = V + (size_t)bh * SDIM * DDIM;

    float acc[8][4];
    #pragma unroll
    for (int i = 0; i < 8; i++)
        #pragma unroll
        for (int j = 0; j < 4; j++) acc[i][j] = 0.0f;

    __syncthreads();   // invs ready

    for (int kk = 0; kk < SDIM; kk += 64) {
        // Load attn tile 128x64, normalize, write back, stage to smem.
        #pragma unroll
        for (int i = 0; i < 8; i++) {
            int e  = tid + i*256;
            int r  = e >> 4;
            int cc = e & 15;
            float4 v = *(const float4*)&Abase[(size_t)r*SDIM + kk + cc*4];
            float inv = invs[r];
            v.x *= inv; v.y *= inv; v.z *= inv; v.w *= inv;
            *(float4*)&Abase[(size_t)r*SDIM + kk + cc*4] = v;
            float* dst = &As[r*AP + cc*4];
            dst[0] = v.x; dst[1] = v.y; dst[2] = v.z; dst[3] = v.w;
        }
        // Load V tile 64x64: 1024 float4, 4 per thread.
        #pragma unroll
        for (int i = 0; i < 4; i++) {
            int e  = tid + i*256;
            int r  = e >> 4;
            int cc = e & 15;
            *(float4*)&Vs[r*64 + cc*4] =
                *(const float4*)&Vbase[(size_t)(kk + r)*DDIM + cc*4];
        }
        __syncthreads();

        #pragma unroll 8
        for (int k0 = 0; k0 < 64; k0 += 2) {
            float2 a[8];
            #pragma unroll
            for (int i = 0; i < 8; i++)
                a[i] = *(const float2*)&As[(ty*8+i)*AP + k0];
            float4 b0 = *(const float4*)&Vs[ k0   *64 + tx*4];
            float4 b1 = *(const float4*)&Vs[(k0+1)*64 + tx*4];
            #pragma unroll
            for (int i = 0; i < 8; i++) {
                acc[i][0] += a[i].x * b0.x;  acc[i][1] += a[i].x * b0.y;
                acc[i][2] += a[i].x * b0.z;  acc[i][3] += a[i].x * b0.w;
                acc[i][0] += a[i].y * b1.x;  acc[i][1] += a[i].y * b1.y;
                acc[i][2] += a[i].y * b1.z;  acc[i][3] += a[i].y * b1.w;
            }
        }
        __syncthreads();
    }

    #pragma unroll
    for (int i = 0; i < 8; i++) {
        int row = qt*128 + ty*8 + i;
        float4 o;
        o.x = acc[i][0]; o.y = acc[i][1]; o.z = acc[i][2]; o.w = acc[i][3];
        *(float4*)&out[((size_t)bh*SDIM + row)*DDIM + tx*4] = o;
    }
}

// ---------------------------------------------------------------------------
// Launch
// ---------------------------------------------------------------------------
extern "C" void kernel_launch(void* const* d_in, const int* in_sizes, int n_in,
                              void* d_out, int out_size)
{
    (void)in_sizes; (void)n_in; (void)out_size;
    const float* Q    = (const float*)d_in[0];
    const float* K    = (const float*)d_in[1];
    const float* V    = (const float*)d_in[2];
    const int*   mask = (const int*)d_in[3];

    float* out  = (float*)d_out;
    float* attn = out + OUT_ELEMS;   // reference returns (out, attn) concatenated

    cudaFuncSetAttribute(k_scores_exp, cudaFuncAttributeMaxDynamicSharedMemorySize, SMEM1_BYTES);
    cudaFuncSetAttribute(k_pv_norm,    cudaFuncAttributeMaxDynamicSharedMemorySize, SMEM3_BYTES);

    k_scores_exp<<<dim3(SDIM/128, BH), 256, SMEM1_BYTES>>>(Q, K, mask, attn);
    k_pv_norm  <<<dim3(SDIM/128, BH), 256, SMEM3_BYTES>>>(attn, V, out);
}

// round 5
// speedup vs baseline: 1.4538x; 1.3941x over previous
#include <cuda_runtime.h>
#include <cuda_bf16.h>
#include <cstdint>

#define BDIM 4
#define HDIM 16
#define SDIM 2048
#define DDIM 64
#define BH   (BDIM*HDIM)                  // 64
#define OUT_ELEMS ((size_t)BH*SDIM*DDIM)  // 8388608
#define SCALE 0.125f

// ---------------- scratch (__device__ globals; allocation-free) ----------------
__device__ float         g_rowsum[(size_t)BH*SDIM];
__device__ __nv_bfloat16 g_vt_hi[(size_t)BH*DDIM*SDIM];   // V^T hi  [bh][n][k]
__device__ __nv_bfloat16 g_vt_lo[(size_t)BH*DDIM*SDIM];   // V^T lo

// ---------------- helpers ----------------
__device__ __forceinline__ uint32_t smem_u32(const void* p){
    uint32_t a;
    asm("{ .reg .u64 t; cvta.to.shared.u64 t, %1; cvt.u32.u64 %0, t; }" : "=r"(a) : "l"(p));
    return a;
}
__device__ __forceinline__ uint32_t pk(__nv_bfloat16 a, __nv_bfloat16 b){
    return (uint32_t)__bfloat16_as_ushort(a) | ((uint32_t)__bfloat16_as_ushort(b) << 16);
}
__device__ __forceinline__ void split_bf(float x, __nv_bfloat16& h, __nv_bfloat16& l){
    h = __float2bfloat16(x);
    l = __float2bfloat16(x - __bfloat162float(h));
}
// Swizzled byte offset for tiles with 128B rows (64 bf16): r = row, ch = 16B chunk.
__device__ __forceinline__ uint32_t swoff(int r, int ch){
    return (uint32_t)((r << 7) + (((ch ^ (r & 7)) & 7) << 4));
}
// Convert 8 floats -> 8 bf16 hi + 8 bf16 lo (packed uint4 each).
__device__ __forceinline__ void cvt8(const float4 v0, const float4 v1, uint4& h, uint4& lo){
    float x[8] = {v0.x, v0.y, v0.z, v0.w, v1.x, v1.y, v1.z, v1.w};
    uint32_t hw[4], lw[4];
    #pragma unroll
    for (int i = 0; i < 4; i++) {
        __nv_bfloat16 h0, l0, h1, l1;
        split_bf(x[2*i], h0, l0);
        split_bf(x[2*i+1], h1, l1);
        hw[i] = pk(h0, h1);
        lw[i] = pk(l0, l1);
    }
    h  = make_uint4(hw[0], hw[1], hw[2], hw[3]);
    lo = make_uint4(lw[0], lw[1], lw[2], lw[3]);
}

#define LDM4(r0, r1, r2, r3, addr)                                          \
    asm volatile("ldmatrix.sync.aligned.m8n8.x4.shared.b16 {%0,%1,%2,%3}, [%4];" \
        : "=r"(r0), "=r"(r1), "=r"(r2), "=r"(r3) : "r"(addr))

#define MMA(d, a, b)                                                        \
    asm volatile("mma.sync.aligned.m16n8k16.row.col.f32.bf16.bf16.f32 "     \
        "{%0,%1,%2,%3}, {%4,%5,%6,%7}, {%8,%9}, {%0,%1,%2,%3};"             \
        : "+f"((d)[0]), "+f"((d)[1]), "+f"((d)[2]), "+f"((d)[3])            \
        : "r"((a)[0]), "r"((a)[1]), "r"((a)[2]), "r"((a)[3]),               \
          "r"((b)[0]), "r"((b)[1]))

// ===========================================================================
// Kernel 0: V^T transpose + bf16 hi/lo split.  grid (32, 64), 256 thr.
// ===========================================================================
__global__ __launch_bounds__(256) void k_vt(const float* __restrict__ V)
{
    const int bh = blockIdx.y;
    const int k0 = blockIdx.x * 64;
    const int tid = threadIdx.x;
    __shared__ float t[64][65];

    const float4* Vv = (const float4*)(V + ((size_t)bh*SDIM + k0)*DDIM);
    #pragma unroll
    for (int i = 0; i < 4; i++) {
        int e = tid + i*256;
        int r = e >> 4, c = (e & 15)*4;
        float4 v = Vv[e];
        t[r][c] = v.x; t[r][c+1] = v.y; t[r][c+2] = v.z; t[r][c+3] = v.w;
    }
    __syncthreads();

    const int n  = tid >> 2;
    const int kq = (tid & 3) * 16;
    uint32_t hw[8], lw[8];
    #pragma unroll
    for (int j = 0; j < 16; j += 2) {
        __nv_bfloat16 h0, l0, h1, l1;
        split_bf(t[kq+j  ][n], h0, l0);
        split_bf(t[kq+j+1][n], h1, l1);
        hw[j>>1] = pk(h0, h1);
        lw[j>>1] = pk(l0, l1);
    }
    size_t base = ((size_t)bh*DDIM + n)*SDIM + k0 + kq;
    uint4* dh = (uint4*)(g_vt_hi + base);
    uint4* dl = (uint4*)(g_vt_lo + base);
    dh[0] = make_uint4(hw[0], hw[1], hw[2], hw[3]);
    dh[1] = make_uint4(hw[4], hw[5], hw[6], hw[7]);
    dl[0] = make_uint4(lw[0], lw[1], lw[2], lw[3]);
    dl[1] = make_uint4(lw[4], lw[5], lw[6], lw[7]);
}

// ===========================================================================
// Kernel 1: attn_raw = mask ? exp(scale * Q K^T) : 0  + row sums.
// 256 thr = 8 warps, warp grid 4(m) x 2(n), warp tile 32x64.
// smem (64KB dyn): Qh@0 Ql@16K Kh@32K Kl@48K, each [128 rows][64 bf16] swizzled.
// ===========================================================================
#define K1_DYN (64*1024)

__global__ __launch_bounds__(256, 2) void k1_scores(
    const float* __restrict__ Q, const float* __restrict__ K,
    const int* __restrict__ mask, float* __restrict__ attn)
{
    extern __shared__ char dyn[];
    __shared__ float red[128];
    const uint32_t sb = smem_u32(dyn);
    const int tid = threadIdx.x, l = tid & 31, wid = tid >> 5;
    const int wm = wid >> 1, wn = wid & 1;
    const int bh = blockIdx.y, qt = blockIdx.x;

    if (tid < 128) red[tid] = 0.0f;

    // Q convert (pre-scaled by 1/sqrt(d))
    {
        const float4* Qv = (const float4*)(Q + ((size_t)bh*SDIM + (size_t)qt*128)*DDIM);
        #pragma unroll
        for (int i = 0; i < 4; i++) {
            int e = tid + i*256, r = e >> 3, ch = e & 7;
            float4 v0 = Qv[e*2], v1 = Qv[e*2+1];
            v0.x *= SCALE; v0.y *= SCALE; v0.z *= SCALE; v0.w *= SCALE;
            v1.x *= SCALE; v1.y *= SCALE; v1.z *= SCALE; v1.w *= SCALE;
            uint4 h, lo; cvt8(v0, v1, h, lo);
            *(uint4*)(dyn +          swoff(r, ch)) = h;
            *(uint4*)(dyn + 16384 +  swoff(r, ch)) = lo;
        }
    }
    __syncthreads();

    const size_t attn_base = (size_t)bh * SDIM * SDIM;
    const size_t mask_base = (size_t)(bh >> 4) * SDIM * SDIM;
    float rs[2][2] = {{0.f, 0.f}, {0.f, 0.f}};
    float acc[2][8][4];

    for (int kt = 0; kt < 16; kt++) {
        // K tile convert
        const float4* Kv = (const float4*)(K + ((size_t)bh*SDIM + (size_t)kt*128)*DDIM);
        #pragma unroll
        for (int i = 0; i < 4; i++) {
            int e = tid + i*256, r = e >> 3, ch = e & 7;
            float4 v0 = Kv[e*2], v1 = Kv[e*2+1];
            uint4 h, lo; cvt8(v0, v1, h, lo);
            *(uint4*)(dyn + 32768 + swoff(r, ch)) = h;
            *(uint4*)(dyn + 49152 + swoff(r, ch)) = lo;
        }
        __syncthreads();

        #pragma unroll
        for (int i = 0; i < 2; i++)
            #pragma unroll
            for (int j = 0; j < 8; j++)
                #pragma unroll
                for (int r = 0; r < 4; r++) acc[i][j][r] = 0.0f;

        // 3 passes: hi*hi, hi*lo, lo*hi (lo*lo negligible)
        #pragma unroll
        for (int p = 0; p < 3; p++) {
            const uint32_t Ab = sb + (p == 2 ? 16384u : 0u);
            const uint32_t Bb = sb + 32768u + (p == 1 ? 16384u : 0u);
            #pragma unroll
            for (int ks = 0; ks < 4; ks++) {
                uint32_t a[2][4];
                #pragma unroll
                for (int i = 0; i < 2; i++) {
                    int row = wm*32 + i*16 + ((l >> 3) & 1)*8 + (l & 7);
                    int ch  = ks*2 + (l >> 4);
                    LDM4(a[i][0], a[i][1], a[i][2], a[i][3], Ab + swoff(row, ch));
                }
                #pragma unroll
                for (int jp = 0; jp < 4; jp++) {
                    uint32_t b0, b1, b2, b3;
                    int n  = wn*64 + jp*16 + (l >> 4)*8 + (l & 7);
                    int ch = ks*2 + ((l >> 3) & 1);
                    LDM4(b0, b1, b2, b3, Bb + swoff(n, ch));
                    uint32_t bA[2] = {b0, b1}, bB[2] = {b2, b3};
                    MMA(acc[0][jp*2  ], a[0], bA);
                    MMA(acc[0][jp*2+1], a[0], bB);
                    MMA(acc[1][jp*2  ], a[1], bA);
                    MMA(acc[1][jp*2+1], a[1], bB);
                }
            }
        }
        __syncthreads();   // smem reads done before next kt's convert writes

        // epilogue: mask + exp + store + rowsum
        #pragma unroll
        for (int i = 0; i < 2; i++) {
            #pragma unroll
            for (int h = 0; h < 2; h++) {
                const int row = qt*128 + wm*32 + i*16 + (l >> 2) + h*8;
                const int*   mrow = mask + mask_base + (size_t)row*SDIM + kt*128;
                float*       arow = attn + attn_base + (size_t)row*SDIM + kt*128;
                float s = 0.0f;
                #pragma unroll
                for (int j = 0; j < 8; j++) {
                    const int col = wn*64 + j*8 + (l & 3)*2;
                    int2 m = *(const int2*)(mrow + col);
                    float e0 = m.x ? __expf(acc[i][j][h*2  ]) : 0.0f;
                    float e1 = m.y ? __expf(acc[i][j][h*2+1]) : 0.0f;
                    s += e0 + e1;
                    *(float2*)(arow + col) = make_float2(e0, e1);
                }
                rs[i][h] += s;
            }
        }
    }

    // rowsum reduce: 4 lanes share a row; 2 warps (wn) share a row -> smem atomics
    #pragma unroll
    for (int i = 0; i < 2; i++)
        #pragma unroll
        for (int h = 0; h < 2; h++) {
            float v = rs[i][h];
            v += __shfl_xor_sync(0xffffffffu, v, 1);
            v += __shfl_xor_sync(0xffffffffu, v, 2);
            if ((l & 3) == 0)
                atomicAdd(&red[wm*32 + i*16 + (l >> 2) + h*8], v);
        }
    __syncthreads();
    if (tid < 128)
        g_rowsum[(size_t)bh*SDIM + qt*128 + tid] = red[tid];
}

// ===========================================================================
// Kernel 2: out = (attn/rowsum) @ V; rewrite attn normalized in place.
// 256 thr, warp grid 4(m) x 2(n), warp tile 32(q) x 32(d).
// smem (48KB dyn): Ph@0 Pl@16K [128][64], Vh@32K Vl@40K [64][64] (swizzled).
// ===========================================================================
#define K2_DYN (48*1024)

__global__ __launch_bounds__(256, 2) void k2_pv(
    float* __restrict__ attn, float* __restrict__ out)
{
    extern __shared__ char dyn[];
    __shared__ float invs[128];
    const uint32_t sb = smem_u32(dyn);
    const int tid = threadIdx.x, l = tid & 31, wid = tid >> 5;
    const int wm = wid >> 1, wn = wid & 1;
    const int bh = blockIdx.y, qt = blockIdx.x;

    if (tid < 128)
        invs[tid] = 1.0f / g_rowsum[(size_t)bh*SDIM + qt*128 + tid];
    __syncthreads();

    float acc[2][4][4];
    #pragma unroll
    for (int i = 0; i < 2; i++)
        #pragma unroll
        for (int j = 0; j < 4; j++)
            #pragma unroll
            for (int r = 0; r < 4; r++) acc[i][j][r] = 0.0f;

    float* Ag = attn + ((size_t)bh*SDIM + (size_t)qt*128)*SDIM;
    const __nv_bfloat16* vH = g_vt_hi + (size_t)bh*DDIM*SDIM;
    const __nv_bfloat16* vL = g_vt_lo + (size_t)bh*DDIM*SDIM;

    for (int c = 0; c < 32; c++) {
        // P stage: normalize + write back + split to smem
        #pragma unroll
        for (int i = 0; i < 4; i++) {
            int e = tid + i*256, r = e >> 3, ch = e & 7;
            float4* gp = (float4*)(Ag + (size_t)r*SDIM + c*64 + ch*8);
            float4 v0 = gp[0], v1 = gp[1];
            const float inv = invs[r];
            v0.x *= inv; v0.y *= inv; v0.z *= inv; v0.w *= inv;
            v1.x *= inv; v1.y *= inv; v1.z *= inv; v1.w *= inv;
            gp[0] = v0; gp[1] = v1;
            uint4 h, lo; cvt8(v0, v1, h, lo);
            *(uint4*)(dyn +         swoff(r, ch)) = h;
            *(uint4*)(dyn + 16384 + swoff(r, ch)) = lo;
        }
        // V^T stage: [64 n][64 k] bf16 hi/lo
        #pragma unroll
        for (int i = 0; i < 2; i++) {
            int e = tid + i*256, n = e >> 3, ch = e & 7;
            const size_t src = (size_t)n*SDIM + c*64 + ch*8;
            *(uint4*)(dyn + 32768 + swoff(n, ch)) = *(const uint4*)(vH + src);
            *(uint4*)(dyn + 40960 + swoff(n, ch)) = *(const uint4*)(vL + src);
        }
        __syncthreads();

        #pragma unroll
        for (int p = 0; p < 3; p++) {
            const uint32_t Ab = sb + (p == 2 ? 16384u : 0u);
            const uint32_t Bb = sb + 32768u + (p == 1 ? 8192u : 0u);
            #pragma unroll
            for (int ks = 0; ks < 4; ks++) {
                uint32_t a[2][4];
                #pragma unroll
                for (int i = 0; i < 2; i++) {
                    int row = wm*32 + i*16 + ((l >> 3) & 1)*8 + (l & 7);
                    int ch  = ks*2 + (l >> 4);
                    LDM4(a[i][0], a[i][1], a[i][2], a[i][3], Ab + swoff(row, ch));
                }
                #pragma unroll
                for (int jp = 0; jp < 2; jp++) {
                    uint32_t b0, b1, b2, b3;
                    int n  = wn*32 + jp*16 + (l >> 4)*8 + (l & 7);
                    int ch = ks*2 + ((l >> 3) & 1);
                    LDM4(b0, b1, b2, b3, Bb + swoff(n, ch));
                    uint32_t bA[2] = {b0, b1}, bB[2] = {b2, b3};
                    MMA(acc[0][jp*2  ], a[0], bA);
                    MMA(acc[0][jp*2+1], a[0], bB);
                    MMA(acc[1][jp*2  ], a[1], bA);
                    MMA(acc[1][jp*2+1], a[1], bB);
                }
            }
        }
        __syncthreads();
    }

    // epilogue: out writes
    #pragma unroll
    for (int i = 0; i < 2; i++)
        #pragma unroll
        for (int h = 0; h < 2; h++) {
            const int row = qt*128 + wm*32 + i*16 + (l >> 2) + h*8;
            #pragma unroll
            for (int j = 0; j < 4; j++) {
                const int col = wn*32 + j*8 + (l & 3)*2;
                *(float2*)&out[((size_t)bh*SDIM + row)*DDIM + col] =
                    make_float2(acc[i][j][h*2], acc[i][j][h*2+1]);
            }
        }
}

// ===========================================================================
// Launch
// ===========================================================================
extern "C" void kernel_launch(void* const* d_in, const int* in_sizes, int n_in,
                              void* d_out, int out_size)
{
    (void)in_sizes; (void)n_in; (void)out_size;
    const float* Q    = (const float*)d_in[0];
    const float* K    = (const float*)d_in[1];
    const float* V    = (const float*)d_in[2];
    const int*   mask = (const int*)d_in[3];

    float* out  = (float*)d_out;
    float* attn = out + OUT_ELEMS;   // reference returns (out, attn) concatenated

    cudaFuncSetAttribute(k1_scores, cudaFuncAttributeMaxDynamicSharedMemorySize, K1_DYN);
    cudaFuncSetAttribute(k2_pv,     cudaFuncAttributeMaxDynamicSharedMemorySize, K2_DYN);

    k_vt      <<<dim3(32, BH), 256>>>(V);
    k1_scores <<<dim3(SDIM/128, BH), 256, K1_DYN>>>(Q, K, mask, attn);
    k2_pv     <<<dim3(SDIM/128, BH), 256, K2_DYN>>>(attn, out);
}